// round 4
// baseline (speedup 1.0000x reference)
#include <cuda_runtime.h>
#include <math.h>
#include <stdint.h>

#define HH   8
#define SS   1024
#define DDIM 64
#define KG   10
#define NLUT 4096
#define BM   64
#define BN   64
#define STR  72          // smem row stride (floats): 72 ≡ 8 (mod 32) -> LDSM rows tile all banks

#define D_LO (-0.05f)
#define D_HI (10.05f)
#define E_LO (-0.05f)
#define E_HI (5.05f)

__device__ float2 g_lutD[NLUT];
__device__ float2 g_lutE[NLUT];

// ---------------------------------------------------------------------------
// Exact bias function (RBF -> Linear -> exact GELU -> Linear), LUT build only.
// ---------------------------------------------------------------------------
__device__ __forceinline__ float bias_eval(
    float x,
    const float* __restrict__ mu, const float* __restrict__ sg,
    const float* __restrict__ bb,
    const float* __restrict__ W1, const float* __restrict__ b1,
    const float* __restrict__ W2, const float* __restrict__ b2)
{
    float psi[KG];
#pragma unroll
    for (int k = 0; k < KG; k++) {
        float s = sg[k];
        float z = (x + bb[k] - mu[k]) / s;
        psi[k] = expf(-0.5f * z * z) * (0.3989422804014327f / s);
    }
    float o = b2[0];
#pragma unroll
    for (int l = 0; l < KG; l++) {
        float a = b1[l];
#pragma unroll
        for (int k = 0; k < KG; k++) a = fmaf(psi[k], W1[l * KG + k], a);
        float g = 0.5f * a * (1.0f + erff(a * 0.7071067811865476f));
        o = fmaf(g, W2[l], o);
    }
    return o;
}

__global__ void build_lut_kernel(
    const float* __restrict__ muD, const float* __restrict__ sgD, const float* __restrict__ bD,
    const float* __restrict__ muE, const float* __restrict__ sgE, const float* __restrict__ bE,
    const float* __restrict__ W1,  const float* __restrict__ b1,
    const float* __restrict__ W2,  const float* __restrict__ b2)
{
    int i = blockIdx.x * blockDim.x + threadIdx.x;
    if (i >= 2 * NLUT) return;
    int which = i >> 12;
    int e     = i & (NLUT - 1);

    float lo = which ? E_LO : D_LO;
    float hi = which ? E_HI : D_HI;
    float dx = (hi - lo) / (float)(NLUT - 1);
    float x0 = lo + (float)e * dx;

    const float* mu = which ? muE : muD;
    const float* sg = which ? sgE : sgD;
    const float* bb = which ? bE  : bD;

    float f0 = bias_eval(x0,      mu, sg, bb, W1, b1, W2, b2);
    float f1 = bias_eval(x0 + dx, mu, sg, bb, W1, b1, W2, b2);
    float2 entry = make_float2(f0, f1 - f0);
    if (which) g_lutE[e] = entry; else g_lutD[e] = entry;
}

// ---------------------------------------------------------------------------
// tf32 / mma / ldmatrix helpers
// ---------------------------------------------------------------------------
__device__ __forceinline__ uint32_t f2tf(float x) {
    uint32_t r;
    asm("cvt.rna.tf32.f32 %0, %1;" : "=r"(r) : "f"(x));
    return r;
}

__device__ __forceinline__ void split_store(float* ph, float* pl, float x) {
    float hx = __uint_as_float(f2tf(x));
    *ph = hx;
    *pl = __uint_as_float(f2tf(x - hx));
}

__device__ __forceinline__ void mma8(float c[4], const uint32_t a[4],
                                     uint32_t b0, uint32_t b1)
{
    asm volatile(
        "mma.sync.aligned.m16n8k8.row.col.f32.tf32.tf32.f32 "
        "{%0,%1,%2,%3}, {%4,%5,%6,%7}, {%8,%9}, {%0,%1,%2,%3};\n"
        : "+f"(c[0]), "+f"(c[1]), "+f"(c[2]), "+f"(c[3])
        : "r"(a[0]), "r"(a[1]), "r"(a[2]), "r"(a[3]), "r"(b0), "r"(b1));
}

// ldmatrix x4 on b16: with f32 data, lane l receives f32 element (l%4) of row
// (l/4) of the 8x4-f32 submatrix whose 16B row addresses lanes 8i..8i+7 supply.
__device__ __forceinline__ void ldsm4(uint32_t& r0, uint32_t& r1,
                                      uint32_t& r2, uint32_t& r3, uint32_t addr)
{
    asm volatile("ldmatrix.sync.aligned.m8n8.x4.shared.b16 {%0,%1,%2,%3}, [%4];\n"
                 : "=r"(r0), "=r"(r1), "=r"(r2), "=r"(r3) : "r"(addr));
}

__device__ __forceinline__ float bias_term(float x, float lo, float inv,
                                           const float2* __restrict__ lut)
{
    float t = fminf(fmaxf((x - lo) * inv, 0.0f), (float)(NLUT - 1) - 1e-3f);
    int   i = (int)t;
    float f = t - (float)i;
    float2 e = lut[i];
    return fmaf(f, e.y, e.x);
}

// ---------------------------------------------------------------------------
// Fused flash-attention, 3xTF32 mma with LDSM fragment loads.
// Grid (16, 8), 256 threads = 8 warps: warp w -> m16-block (w&3), n32-half (w>>2).
// ---------------------------------------------------------------------------
__global__ __launch_bounds__(256, 1) void attn_kernel(
    const float* __restrict__ Q,
    const float* __restrict__ Kg,
    const float* __restrict__ Vg,
    const float* __restrict__ dist,
    const float* __restrict__ energy,
    const int*   __restrict__ mask,
    float*       __restrict__ out)
{
    extern __shared__ float sm[];
    float* sQh  = sm;
    float* sQl  = sm + 1 * 64 * STR;
    float* sKh  = sm + 2 * 64 * STR;
    float* sKl  = sm + 3 * 64 * STR;
    float* sVth = sm + 4 * 64 * STR;      // V transposed: [d][j]
    float* sVtl = sm + 5 * 64 * STR;
    float* sPh  = sm + 6 * 64 * STR;
    float* sPl  = sm + 7 * 64 * STR;
    float* redmax = sm + 8 * 64 * STR;    // [8 warps][16 rows]
    float* redsum = redmax + 128;
    float* m_s    = redsum + 128;         // [64]
    float* l_s    = m_s + 64;             // [64]
    float2* sLD   = (float2*)(l_s + 64);
    float2* sLE   = sLD + NLUT;

    const int tid   = threadIdx.x;
    const int w     = tid >> 5;
    const int lane  = tid & 31;
    const int g     = lane >> 2;
    const int m     = lane & 3;
    const int mblk  = w & 3;
    const int nhalf = w >> 2;
    const int h     = blockIdx.y;
    const int i0    = blockIdx.x * BM;

    const int lr0 = mblk * 16 + g;
    const int lr1 = lr0 + 8;
    const int r0g = i0 + lr0;

    const float SCALE = 0.08838834764831845f;   // 1/sqrt(2*D)
    const float DINVc = (float)(NLUT - 1) / (D_HI - D_LO);
    const float EINVc = (float)(NLUT - 1) / (E_HI - E_LO);

    // shared-space base addresses for LDSM
    const uint32_t uQh  = (uint32_t)__cvta_generic_to_shared(sQh);
    const uint32_t uQl  = (uint32_t)__cvta_generic_to_shared(sQl);
    const uint32_t uKh  = (uint32_t)__cvta_generic_to_shared(sKh);
    const uint32_t uKl  = (uint32_t)__cvta_generic_to_shared(sKl);
    const uint32_t uVh  = (uint32_t)__cvta_generic_to_shared(sVth);
    const uint32_t uVl  = (uint32_t)__cvta_generic_to_shared(sVtl);
    const uint32_t uPh  = (uint32_t)__cvta_generic_to_shared(sPh);
    const uint32_t uPl  = (uint32_t)__cvta_generic_to_shared(sPl);

    // per-lane LDSM row-address offsets (bytes)
    const int r8   = lane & 7;
    const int msel = lane >> 3;
    // A/P: matrix msel -> rows mblk*16 + (msel&1)*8 + r8, col block (msel>>1)*4
    const uint32_t offA = (uint32_t)(((mblk * 16 + (msel & 1) * 8 + r8) * STR
                                      + (msel >> 1) * 4) * 4);
    // B (K rows j / Vt rows d): matrix msel -> rows nhalf*32 + (msel>>1)*8 + r8,
    // col block (msel&1)*4; +16-row step for the second nt pair
    const uint32_t offB = (uint32_t)(((nhalf * 32 + (msel >> 1) * 8 + r8) * STR
                                      + (msel & 1) * 4) * 4);
    const uint32_t pairStep = 16 * STR * 4;

    // ---- one-time block init ----
    for (int i = tid; i < NLUT; i += 256) { sLD[i] = g_lutD[i]; sLE[i] = g_lutE[i]; }
    if (tid < 64) { m_s[tid] = -1e30f; l_s[tid] = 0.0f; }

#pragma unroll
    for (int it = 0; it < 4; it++) {
        int lin = tid + it * 256;
        int row = lin >> 4, c4 = (lin & 15) * 4;
        float4 qv = *(const float4*)&Q[((size_t)h * SS + i0 + row) * DDIM + c4];
        float* qh = &sQh[row * STR + c4];
        float* ql = &sQl[row * STR + c4];
        split_store(qh + 0, ql + 0, qv.x);
        split_store(qh + 1, ql + 1, qv.y);
        split_store(qh + 2, ql + 2, qv.z);
        split_store(qh + 3, ql + 3, qv.w);
    }

    float oacc[4][4] = {};

    for (int jt = 0; jt < SS / BN; jt++) {
        const int j0 = jt * BN;
        __syncthreads();   // (A) previous tile fully consumed

        // ---- K tile (natural [j][d]) with tf32 split ----
#pragma unroll
        for (int it = 0; it < 4; it++) {
            int lin = tid + it * 256;
            int row = lin >> 4, c4 = (lin & 15) * 4;
            float4 kv = *(const float4*)&Kg[((size_t)h * SS + j0 + row) * DDIM + c4];
            float* kh = &sKh[row * STR + c4];
            float* kl = &sKl[row * STR + c4];
            split_store(kh + 0, kl + 0, kv.x);
            split_store(kh + 1, kl + 1, kv.y);
            split_store(kh + 2, kl + 2, kv.z);
            split_store(kh + 3, kl + 3, kv.w);
        }

        // ---- V tile TRANSPOSED ([d][j]) with tf32 split, conflict-free STS ----
        // lane -> (d = db + lane/4, j = jb + lane%4); banks 8d'+j' all distinct.
#pragma unroll
        for (int t = 0; t < 16; t++) {
            int p  = w * 16 + t;
            int db = (p & 7) * 8, jb = (p >> 3) * 4;
            int d  = db + (lane >> 2);
            int j  = jb + (lane & 3);
            float v  = Vg[((size_t)h * SS + j0 + j) * DDIM + d];
            float hv = __uint_as_float(f2tf(v));
            sVth[d * STR + j] = hv;
            sVtl[d * STR + j] = __uint_as_float(f2tf(v - hv));
        }

        // ---- prefetch bias streams for this thread's 16 S elements ----
        const int jb = j0 + nhalf * 32;
        float2 fD[4][2], fE[4][2];
        int2   fM[4][2];
        {
            size_t ro0 = ((size_t)h * SS + r0g) * SS;
            size_t ro1 = ro0 + (size_t)8 * SS;
#pragma unroll
            for (int nt = 0; nt < 4; nt++) {
                int cc = jb + nt * 8 + 2 * m;
                fD[nt][0] = *(const float2*)&dist[ro0 + cc];
                fD[nt][1] = *(const float2*)&dist[ro1 + cc];
                fE[nt][0] = *(const float2*)&energy[ro0 + cc];
                fE[nt][1] = *(const float2*)&energy[ro1 + cc];
                fM[nt][0] = *(const int2*)&mask[ro0 + cc];
                fM[nt][1] = *(const int2*)&mask[ro1 + cc];
            }
        }
        __syncthreads();   // (B) tiles ready

        // ---- S = Q K^T via 3xTF32 mma, LDSM fragments ----
        float sacc[4][4] = {};
#pragma unroll
        for (int ks = 0; ks < 8; ks++) {
            const uint32_t kb = (uint32_t)(ks * 32);
            uint32_t ah[4], al[4], bh[8], bl[8];
            ldsm4(ah[0], ah[1], ah[2], ah[3], uQh + offA + kb);
            ldsm4(al[0], al[1], al[2], al[3], uQl + offA + kb);
            ldsm4(bh[0], bh[1], bh[2], bh[3], uKh + offB + kb);
            ldsm4(bh[4], bh[5], bh[6], bh[7], uKh + offB + pairStep + kb);
            ldsm4(bl[0], bl[1], bl[2], bl[3], uKl + offB + kb);
            ldsm4(bl[4], bl[5], bl[6], bl[7], uKl + offB + pairStep + kb);
#pragma unroll
            for (int nt = 0; nt < 4; nt++) {
                mma8(sacc[nt], ah, bh[nt * 2], bh[nt * 2 + 1]);
                mma8(sacc[nt], al, bh[nt * 2], bh[nt * 2 + 1]);
                mma8(sacc[nt], ah, bl[nt * 2], bl[nt * 2 + 1]);
            }
        }

        // ---- scale + LUT biases + mask ----
#pragma unroll
        for (int nt = 0; nt < 4; nt++) {
            float v;
            v = sacc[nt][0] * SCALE + bias_term(fD[nt][0].x, D_LO, DINVc, sLD)
                                    + bias_term(fE[nt][0].x, E_LO, EINVc, sLE);
            sacc[nt][0] = fM[nt][0].x ? v : -1e9f;
            v = sacc[nt][1] * SCALE + bias_term(fD[nt][0].y, D_LO, DINVc, sLD)
                                    + bias_term(fE[nt][0].y, E_LO, EINVc, sLE);
            sacc[nt][1] = fM[nt][0].y ? v : -1e9f;
            v = sacc[nt][2] * SCALE + bias_term(fD[nt][1].x, D_LO, DINVc, sLD)
                                    + bias_term(fE[nt][1].x, E_LO, EINVc, sLE);
            sacc[nt][2] = fM[nt][1].x ? v : -1e9f;
            v = sacc[nt][3] * SCALE + bias_term(fD[nt][1].y, D_LO, DINVc, sLD)
                                    + bias_term(fE[nt][1].y, E_LO, EINVc, sLE);
            sacc[nt][3] = fM[nt][1].y ? v : -1e9f;
        }

        // ---- per-warp row maxima ----
        float mx0 = fmaxf(fmaxf(sacc[0][0], sacc[0][1]), fmaxf(sacc[1][0], sacc[1][1]));
        float mx1 = fmaxf(fmaxf(sacc[0][2], sacc[0][3]), fmaxf(sacc[1][2], sacc[1][3]));
        mx0 = fmaxf(mx0, fmaxf(fmaxf(sacc[2][0], sacc[2][1]), fmaxf(sacc[3][0], sacc[3][1])));
        mx1 = fmaxf(mx1, fmaxf(fmaxf(sacc[2][2], sacc[2][3]), fmaxf(sacc[3][2], sacc[3][3])));
#pragma unroll
        for (int o = 1; o < 4; o <<= 1) {
            mx0 = fmaxf(mx0, __shfl_xor_sync(0xffffffffu, mx0, o));
            mx1 = fmaxf(mx1, __shfl_xor_sync(0xffffffffu, mx1, o));
        }
        if (m == 0) { redmax[w * 16 + g] = mx0; redmax[w * 16 + 8 + g] = mx1; }
        __syncthreads();   // (C)

        // ---- combine halves, exp, P store (split), row sums ----
        const int wp = w ^ 4;
        float mo0 = m_s[lr0], mo1 = m_s[lr1];
        float mn0 = fmaxf(mo0, fmaxf(redmax[w * 16 + g],     redmax[wp * 16 + g]));
        float mn1 = fmaxf(mo1, fmaxf(redmax[w * 16 + 8 + g], redmax[wp * 16 + 8 + g]));
        float al0 = __expf(mo0 - mn0), al1 = __expf(mo1 - mn1);

        float sum0 = 0.0f, sum1 = 0.0f;
#pragma unroll
        for (int nt = 0; nt < 4; nt++) {
            float p0 = __expf(sacc[nt][0] - mn0);
            float p1 = __expf(sacc[nt][1] - mn0);
            float p2 = __expf(sacc[nt][2] - mn1);
            float p3 = __expf(sacc[nt][3] - mn1);
            sum0 += p0 + p1;  sum1 += p2 + p3;

            int jl = nhalf * 32 + nt * 8 + 2 * m;
            float h0 = __uint_as_float(f2tf(p0)), h1 = __uint_as_float(f2tf(p1));
            float h2 = __uint_as_float(f2tf(p2)), h3 = __uint_as_float(f2tf(p3));
            *(float2*)&sPh[lr0 * STR + jl] = make_float2(h0, h1);
            *(float2*)&sPh[lr1 * STR + jl] = make_float2(h2, h3);
            *(float2*)&sPl[lr0 * STR + jl] =
                make_float2(__uint_as_float(f2tf(p0 - h0)), __uint_as_float(f2tf(p1 - h1)));
            *(float2*)&sPl[lr1 * STR + jl] =
                make_float2(__uint_as_float(f2tf(p2 - h2)), __uint_as_float(f2tf(p3 - h3)));
        }
#pragma unroll
        for (int o = 1; o < 4; o <<= 1) {
            sum0 += __shfl_xor_sync(0xffffffffu, sum0, o);
            sum1 += __shfl_xor_sync(0xffffffffu, sum1, o);
        }
        if (m == 0) { redsum[w * 16 + g] = sum0; redsum[w * 16 + 8 + g] = sum1; }
        __syncthreads();   // (D) redsum + P ready

        if (nhalf == 0 && m == 0) {
            l_s[lr0] = l_s[lr0] * al0 + redsum[w * 16 + g] + redsum[(w + 4) * 16 + g];
            l_s[lr1] = l_s[lr1] * al1 + redsum[w * 16 + 8 + g] + redsum[(w + 4) * 16 + 8 + g];
            m_s[lr0] = mn0;
            m_s[lr1] = mn1;
        }

        // ---- rescale O, then O += P V via 3xTF32 mma, LDSM fragments ----
#pragma unroll
        for (int nt = 0; nt < 4; nt++) {
            oacc[nt][0] *= al0;  oacc[nt][1] *= al0;
            oacc[nt][2] *= al1;  oacc[nt][3] *= al1;
        }
#pragma unroll
        for (int ks = 0; ks < 8; ks++) {
            const uint32_t kb = (uint32_t)(ks * 32);
            uint32_t ah[4], al_[4], bh[8], bl[8];
            ldsm4(ah[0],  ah[1],  ah[2],  ah[3],  uPh + offA + kb);
            ldsm4(al_[0], al_[1], al_[2], al_[3], uPl + offA + kb);
            ldsm4(bh[0], bh[1], bh[2], bh[3], uVh + offB + kb);
            ldsm4(bh[4], bh[5], bh[6], bh[7], uVh + offB + pairStep + kb);
            ldsm4(bl[0], bl[1], bl[2], bl[3], uVl + offB + kb);
            ldsm4(bl[4], bl[5], bl[6], bl[7], uVl + offB + pairStep + kb);
#pragma unroll
            for (int nt = 0; nt < 4; nt++) {
                mma8(oacc[nt], ah,  bh[nt * 2], bh[nt * 2 + 1]);
                mma8(oacc[nt], al_, bh[nt * 2], bh[nt * 2 + 1]);
                mma8(oacc[nt], ah,  bl[nt * 2], bl[nt * 2 + 1]);
            }
        }
    }

    // ---- normalize + write output ----
    __syncthreads();
    float inv0 = 1.0f / l_s[lr0];
    float inv1 = 1.0f / l_s[lr1];
#pragma unroll
    for (int nt = 0; nt < 4; nt++) {
        int dl = nhalf * 32 + nt * 8 + 2 * m;
        size_t o0 = ((size_t)h * SS + r0g) * DDIM + dl;
        *(float2*)&out[o0]            = make_float2(oacc[nt][0] * inv0, oacc[nt][1] * inv0);
        *(float2*)&out[o0 + 8 * DDIM] = make_float2(oacc[nt][2] * inv1, oacc[nt][3] * inv1);
    }
}

// ---------------------------------------------------------------------------
extern "C" void kernel_launch(void* const* d_in, const int* in_sizes, int n_in,
                              void* d_out, int out_size)
{
    const float* Q      = (const float*)d_in[0];
    const float* K      = (const float*)d_in[1];
    const float* V      = (const float*)d_in[2];
    const float* dist   = (const float*)d_in[3];
    const float* energy = (const float*)d_in[4];
    const int*   mask   = (const int*)  d_in[5];
    const float* mu_D   = (const float*)d_in[6];
    const float* sg_D   = (const float*)d_in[7];
    const float* b_D    = (const float*)d_in[8];
    const float* mu_E   = (const float*)d_in[9];
    const float* sg_E   = (const float*)d_in[10];
    const float* b_E    = (const float*)d_in[11];
    const float* W1     = (const float*)d_in[12];
    const float* b1     = (const float*)d_in[13];
    const float* W2     = (const float*)d_in[14];
    const float* b2     = (const float*)d_in[15];
    float* out = (float*)d_out;

    build_lut_kernel<<<(2 * NLUT + 255) / 256, 256>>>(
        mu_D, sg_D, b_D, mu_E, sg_E, b_E, W1, b1, W2, b2);

    const int SMEM_BYTES = (8 * 64 * STR + 128 + 128 + 64 + 64) * 4 + 2 * NLUT * 8;
    cudaFuncSetAttribute(attn_kernel,
                         cudaFuncAttributeMaxDynamicSharedMemorySize, SMEM_BYTES);
    attn_kernel<<<dim3(SS / BM, HH), 256, SMEM_BYTES>>>(
        Q, K, V, dist, energy, mask, out);
}

// round 6
// speedup vs baseline: 1.5605x; 1.5605x over previous
#include <cuda_runtime.h>
#include <cuda_bf16.h>
#include <math.h>
#include <stdint.h>

#define HH   8
#define SS   1024
#define DDIM 64
#define KG   10
#define NLUT 2048
#define BM   32
#define BN   64
#define STRB 72            // bf16 tile row stride (144B) -> conflict-free ldmatrix

#define D_LO (-0.05f)
#define D_HI (10.05f)
#define E_LO (-0.05f)
#define E_HI (5.05f)

__device__ float2 g_lutD[NLUT];
__device__ float2 g_lutE[NLUT];

// ---------------------------------------------------------------------------
// Exact bias (RBF -> Linear -> exact GELU -> Linear), LUT build only.
// ---------------------------------------------------------------------------
__device__ __forceinline__ float bias_eval(
    float x,
    const float* __restrict__ mu, const float* __restrict__ sg,
    const float* __restrict__ bb,
    const float* __restrict__ W1, const float* __restrict__ b1,
    const float* __restrict__ W2, const float* __restrict__ b2)
{
    float psi[KG];
#pragma unroll
    for (int k = 0; k < KG; k++) {
        float s = sg[k];
        float z = (x + bb[k] - mu[k]) / s;
        psi[k] = expf(-0.5f * z * z) * (0.3989422804014327f / s);
    }
    float o = b2[0];
#pragma unroll
    for (int l = 0; l < KG; l++) {
        float a = b1[l];
#pragma unroll
        for (int k = 0; k < KG; k++) a = fmaf(psi[k], W1[l * KG + k], a);
        float g = 0.5f * a * (1.0f + erff(a * 0.7071067811865476f));
        o = fmaf(g, W2[l], o);
    }
    return o;
}

__global__ void build_lut_kernel(
    const float* __restrict__ muD, const float* __restrict__ sgD, const float* __restrict__ bD,
    const float* __restrict__ muE, const float* __restrict__ sgE, const float* __restrict__ bE,
    const float* __restrict__ W1,  const float* __restrict__ b1,
    const float* __restrict__ W2,  const float* __restrict__ b2)
{
    int i = blockIdx.x * blockDim.x + threadIdx.x;
    if (i >= 2 * NLUT) return;
    int which = i >= NLUT;
    int e     = i & (NLUT - 1);

    float lo = which ? E_LO : D_LO;
    float hi = which ? E_HI : D_HI;
    float dx = (hi - lo) / (float)(NLUT - 1);
    float x0 = lo + (float)e * dx;

    const float* mu = which ? muE : muD;
    const float* sg = which ? sgE : sgD;
    const float* bb = which ? bE  : bD;

    float f0 = bias_eval(x0,      mu, sg, bb, W1, b1, W2, b2);
    float f1 = bias_eval(x0 + dx, mu, sg, bb, W1, b1, W2, b2);
    float2 entry = make_float2(f0, f1 - f0);
    if (which) g_lutE[e] = entry; else g_lutD[e] = entry;
}

// ---------------------------------------------------------------------------
// bf16 / mma / ldmatrix helpers
// ---------------------------------------------------------------------------
__device__ __forceinline__ float bf16of(float x) {
    return __bfloat162float(__float2bfloat16(x));
}
// pack (lo -> bits[15:0], hi -> bits[31:16]); memory order lo,hi
__device__ __forceinline__ uint32_t pack2(float lo, float hi) {
    uint32_t r;
    asm("cvt.rn.bf16x2.f32 %0, %1, %2;" : "=r"(r) : "f"(hi), "f"(lo));
    return r;
}

__device__ __forceinline__ void mma16(float c[4], const uint32_t a[4],
                                      uint32_t b0, uint32_t b1)
{
    asm volatile(
        "mma.sync.aligned.m16n8k16.row.col.f32.bf16.bf16.f32 "
        "{%0,%1,%2,%3}, {%4,%5,%6,%7}, {%8,%9}, {%0,%1,%2,%3};\n"
        : "+f"(c[0]), "+f"(c[1]), "+f"(c[2]), "+f"(c[3])
        : "r"(a[0]), "r"(a[1]), "r"(a[2]), "r"(a[3]), "r"(b0), "r"(b1));
}

__device__ __forceinline__ void ldsm4(uint32_t r[4], uint32_t addr) {
    asm volatile("ldmatrix.sync.aligned.m8n8.x4.shared.b16 {%0,%1,%2,%3}, [%4];\n"
                 : "=r"(r[0]), "=r"(r[1]), "=r"(r[2]), "=r"(r[3]) : "r"(addr));
}
__device__ __forceinline__ void ldsm4t(uint32_t r[4], uint32_t addr) {
    asm volatile("ldmatrix.sync.aligned.m8n8.x4.trans.shared.b16 {%0,%1,%2,%3}, [%4];\n"
                 : "=r"(r[0]), "=r"(r[1]), "=r"(r[2]), "=r"(r[3]) : "r"(addr));
}

__device__ __forceinline__ float bias_term(float x, float lo, float inv,
                                           const float2* __restrict__ lut)
{
    float t = fminf(fmaxf((x - lo) * inv, 0.0f), (float)(NLUT - 1) - 1e-3f);
    int   i = (int)t;
    float f = t - (float)i;
    float2 e = lut[i];
    return fmaf(f, e.y, e.x);
}

// split float4 -> hi/lo bf16x2 pairs, one uint2 store each
__device__ __forceinline__ void split_store4(uint32_t* ph, uint32_t* pl, float4 v)
{
    float h0 = bf16of(v.x), h1 = bf16of(v.y), h2 = bf16of(v.z), h3 = bf16of(v.w);
    *(uint2*)ph = make_uint2(pack2(h0, h1), pack2(h2, h3));
    *(uint2*)pl = make_uint2(pack2(v.x - h0, v.y - h1), pack2(v.z - h2, v.w - h3));
}

// smem byte offsets
#define SO_QH  0
#define SO_QL  4608
#define SO_KH  9216
#define SO_KL  18432
#define SO_VH  27648
#define SO_VL  36864
#define SO_PH  46080
#define SO_PL  50688
#define SO_RMX 55296
#define SO_RSM 55808
#define SO_MS  56320
#define SO_LS  56448
#define SO_LD  56576
#define SO_LE  (56576 + NLUT * 8)
#define SMEM_TOTAL (SO_LE + NLUT * 8)

// ---------------------------------------------------------------------------
// Fused flash-attention: bf16 double-double mma, BM=32, grid 256 CTAs.
// 8 warps: mblk = w&1 (m16 block), nq = w>>1 (n16 block of BN=64).
// ---------------------------------------------------------------------------
__global__ __launch_bounds__(256, 2) void attn_kernel(
    const float* __restrict__ Q,
    const float* __restrict__ Kg,
    const float* __restrict__ Vg,
    const float* __restrict__ dist,
    const float* __restrict__ energy,
    const int*   __restrict__ mask,
    float*       __restrict__ out)
{
    extern __shared__ char smb[];
    uint32_t* tQh = (uint32_t*)(smb + SO_QH);
    uint32_t* tQl = (uint32_t*)(smb + SO_QL);
    uint32_t* tKh = (uint32_t*)(smb + SO_KH);
    uint32_t* tKl = (uint32_t*)(smb + SO_KL);
    uint32_t* tVh = (uint32_t*)(smb + SO_VH);
    uint32_t* tVl = (uint32_t*)(smb + SO_VL);
    uint32_t* tPh = (uint32_t*)(smb + SO_PH);
    uint32_t* tPl = (uint32_t*)(smb + SO_PL);
    float* redmax = (float*)(smb + SO_RMX);     // [8][16]
    float* redsum = (float*)(smb + SO_RSM);
    float* m_s    = (float*)(smb + SO_MS);      // [32]
    float* l_s    = (float*)(smb + SO_LS);      // [32]
    float2* sLD   = (float2*)(smb + SO_LD);
    float2* sLE   = (float2*)(smb + SO_LE);

    const int tid  = threadIdx.x;
    const int w    = tid >> 5;
    const int lane = tid & 31;
    const int g    = lane >> 2;
    const int m    = lane & 3;
    const int mblk = w & 1;
    const int nq   = w >> 1;
    const int h    = blockIdx.y;
    const int i0   = blockIdx.x * BM;

    const int lr0 = mblk * 16 + g;
    const int lr1 = lr0 + 8;
    const int r0g = i0 + lr0;

    const float SCALE = 0.08838834764831845f;   // 1/sqrt(2*D)
    const float DINVc = (float)(NLUT - 1) / (D_HI - D_LO);
    const float EINVc = (float)(NLUT - 1) / (E_HI - E_LO);

    const uint32_t uBase = (uint32_t)__cvta_generic_to_shared(smb);
    const int r8   = lane & 7;
    const int msel = lane >> 3;
    // A (Q/P): groups -> a0..a3 of m16n8k16
    const uint32_t offA  = (uint32_t)(((mblk * 16 + (msel & 1) * 8 + r8) * STRB
                                       + (msel >> 1) * 8) * 2);
    // B from K (normal ldsm): r0=b0(nt0), r1=b0(nt1), r2=b1(nt0), r3=b1(nt1)
    const uint32_t offBK = (uint32_t)(((nq * 16 + (msel & 1) * 8 + r8) * STRB
                                       + (msel >> 1) * 8) * 2);
    // B from V (trans ldsm): r0=b0(nt0), r1=b1(nt0), r2=b0(nt1), r3=b1(nt1)
    const uint32_t offBV = (uint32_t)((((msel & 1) * 8 + r8) * STRB
                                       + nq * 16 + (msel >> 1) * 8) * 2);

    // ---- one-time init: LUTs, stats, Q tile ----
    for (int i = tid; i < NLUT; i += 256) { sLD[i] = g_lutD[i]; sLE[i] = g_lutE[i]; }
    if (tid < 32) { m_s[tid] = -1e30f; l_s[tid] = 0.0f; }

#pragma unroll
    for (int it = 0; it < 2; it++) {
        int lin = tid + it * 256;               // 512 chunks: 32 rows x 16 float4
        int row = lin >> 4, c4 = (lin & 15) * 4;
        float4 qv = *(const float4*)&Q[((size_t)h * SS + i0 + row) * DDIM + c4];
        int wi = row * 36 + (c4 >> 1);
        split_store4(&tQh[wi], &tQl[wi], qv);
    }

    float oacc[2][4] = {};

    for (int jt = 0; jt < SS / BN; jt++) {
        const int j0 = jt * BN;
        __syncthreads();   // (A) previous tile fully consumed

        // ---- bias stream loads FIRST (in flight through fills + mma) ----
        const int cb = j0 + nq * 16 + 2 * m;
        float2 fD[2][2], fE[2][2];
        int2   fM[2][2];
        {
            size_t ro0 = ((size_t)h * SS + r0g) * SS;
            size_t ro1 = ro0 + (size_t)8 * SS;
#pragma unroll
            for (int nt = 0; nt < 2; nt++) {
                int cc = cb + nt * 8;
                fD[nt][0] = *(const float2*)&dist[ro0 + cc];
                fD[nt][1] = *(const float2*)&dist[ro1 + cc];
                fE[nt][0] = *(const float2*)&energy[ro0 + cc];
                fE[nt][1] = *(const float2*)&energy[ro1 + cc];
                fM[nt][0] = *(const int2*)&mask[ro0 + cc];
                fM[nt][1] = *(const int2*)&mask[ro1 + cc];
            }
        }

        // ---- K,V tiles (natural [j][d]) -> bf16 hi/lo ----
#pragma unroll
        for (int it = 0; it < 4; it++) {
            int lin = tid + it * 256;           // 1024 chunks: 64 rows x 16 float4
            int row = lin >> 4, c4 = (lin & 15) * 4;
            size_t goff = ((size_t)h * SS + j0 + row) * DDIM + c4;
            float4 kv = *(const float4*)&Kg[goff];
            float4 vv = *(const float4*)&Vg[goff];
            int wi = row * 36 + (c4 >> 1);
            split_store4(&tKh[wi], &tKl[wi], kv);
            split_store4(&tVh[wi], &tVl[wi], vv);
        }
        __syncthreads();   // (B) tiles ready

        // ---- S = Q K^T : bf16 double-double (hh + lh + hl) ----
        float sacc[2][4] = {};
#pragma unroll
        for (int ki = 0; ki < 4; ki++) {
            const uint32_t kb = (uint32_t)(ki * 32);
            uint32_t ah[4], al[4], bh[4], bl[4];
            ldsm4(ah, uBase + SO_QH + offA + kb);
            ldsm4(al, uBase + SO_QL + offA + kb);
            ldsm4(bh, uBase + SO_KH + offBK + kb);
            ldsm4(bl, uBase + SO_KL + offBK + kb);
            mma16(sacc[0], ah, bh[0], bh[2]);
            mma16(sacc[0], al, bh[0], bh[2]);
            mma16(sacc[0], ah, bl[0], bl[2]);
            mma16(sacc[1], ah, bh[1], bh[3]);
            mma16(sacc[1], al, bh[1], bh[3]);
            mma16(sacc[1], ah, bl[1], bl[3]);
        }

        // ---- scale + LUT biases + mask ----
#pragma unroll
        for (int nt = 0; nt < 2; nt++) {
            float v;
            v = sacc[nt][0] * SCALE + bias_term(fD[nt][0].x, D_LO, DINVc, sLD)
                                    + bias_term(fE[nt][0].x, E_LO, EINVc, sLE);
            sacc[nt][0] = fM[nt][0].x ? v : -1e9f;
            v = sacc[nt][1] * SCALE + bias_term(fD[nt][0].y, D_LO, DINVc, sLD)
                                    + bias_term(fE[nt][0].y, E_LO, EINVc, sLE);
            sacc[nt][1] = fM[nt][0].y ? v : -1e9f;
            v = sacc[nt][2] * SCALE + bias_term(fD[nt][1].x, D_LO, DINVc, sLD)
                                    + bias_term(fE[nt][1].x, E_LO, EINVc, sLE);
            sacc[nt][2] = fM[nt][1].x ? v : -1e9f;
            v = sacc[nt][3] * SCALE + bias_term(fD[nt][1].y, D_LO, DINVc, sLD)
                                    + bias_term(fE[nt][1].y, E_LO, EINVc, sLE);
            sacc[nt][3] = fM[nt][1].y ? v : -1e9f;
        }

        // ---- per-warp row maxima (reduce over m lanes) ----
        float mx0 = fmaxf(fmaxf(sacc[0][0], sacc[0][1]), fmaxf(sacc[1][0], sacc[1][1]));
        float mx1 = fmaxf(fmaxf(sacc[0][2], sacc[0][3]), fmaxf(sacc[1][2], sacc[1][3]));
        mx0 = fmaxf(mx0, __shfl_xor_sync(0xffffffffu, mx0, 1));
        mx0 = fmaxf(mx0, __shfl_xor_sync(0xffffffffu, mx0, 2));
        mx1 = fmaxf(mx1, __shfl_xor_sync(0xffffffffu, mx1, 1));
        mx1 = fmaxf(mx1, __shfl_xor_sync(0xffffffffu, mx1, 2));
        if (m == 0) { redmax[w * 16 + g] = mx0; redmax[w * 16 + 8 + g] = mx1; }
        __syncthreads();   // (C)

        // ---- combine 4 warps sharing mblk, exp, P store, row sums ----
        float mo0 = m_s[lr0], mo1 = m_s[lr1];
        float mn0 = mo0, mn1 = mo1;
#pragma unroll
        for (int ww = 0; ww < 4; ww++) {
            mn0 = fmaxf(mn0, redmax[(mblk + 2 * ww) * 16 + g]);
            mn1 = fmaxf(mn1, redmax[(mblk + 2 * ww) * 16 + 8 + g]);
        }
        float al0 = __expf(mo0 - mn0), al1 = __expf(mo1 - mn1);

        float sum0 = 0.0f, sum1 = 0.0f;
#pragma unroll
        for (int nt = 0; nt < 2; nt++) {
            float p0 = __expf(sacc[nt][0] - mn0);
            float p1 = __expf(sacc[nt][1] - mn0);
            float p2 = __expf(sacc[nt][2] - mn1);
            float p3 = __expf(sacc[nt][3] - mn1);
            sum0 += p0 + p1;  sum1 += p2 + p3;

            int col = nq * 16 + nt * 8 + 2 * m;
            float h0 = bf16of(p0), h1 = bf16of(p1);
            float h2 = bf16of(p2), h3 = bf16of(p3);
            tPh[lr0 * 36 + (col >> 1)] = pack2(h0, h1);
            tPh[lr1 * 36 + (col >> 1)] = pack2(h2, h3);
            tPl[lr0 * 36 + (col >> 1)] = pack2(p0 - h0, p1 - h1);
            tPl[lr1 * 36 + (col >> 1)] = pack2(p2 - h2, p3 - h3);
        }
        sum0 += __shfl_xor_sync(0xffffffffu, sum0, 1);
        sum0 += __shfl_xor_sync(0xffffffffu, sum0, 2);
        sum1 += __shfl_xor_sync(0xffffffffu, sum1, 1);
        sum1 += __shfl_xor_sync(0xffffffffu, sum1, 2);
        if (m == 0) { redsum[w * 16 + g] = sum0; redsum[w * 16 + 8 + g] = sum1; }
        __syncthreads();   // (D) P + redsum ready

        if (w < 2 && m == 0) {
            float s0 = 0.0f, s1 = 0.0f;
#pragma unroll
            for (int ww = 0; ww < 4; ww++) {
                s0 += redsum[(mblk + 2 * ww) * 16 + g];
                s1 += redsum[(mblk + 2 * ww) * 16 + 8 + g];
            }
            l_s[lr0] = l_s[lr0] * al0 + s0;
            l_s[lr1] = l_s[lr1] * al1 + s1;
            m_s[lr0] = mn0;
            m_s[lr1] = mn1;
        }

        // ---- rescale O, then O += P V (bf16 double-double) ----
#pragma unroll
        for (int nt = 0; nt < 2; nt++) {
            oacc[nt][0] *= al0;  oacc[nt][1] *= al0;
            oacc[nt][2] *= al1;  oacc[nt][3] *= al1;
        }
#pragma unroll
        for (int ki = 0; ki < 4; ki++) {
            const uint32_t kb  = (uint32_t)(ki * 32);
            const uint32_t kbV = (uint32_t)(ki * 16 * STRB * 2);
            uint32_t ah[4], al_[4], bh[4], bl[4];
            ldsm4(ah,  uBase + SO_PH + offA + kb);
            ldsm4(al_, uBase + SO_PL + offA + kb);
            ldsm4t(bh, uBase + SO_VH + offBV + kbV);
            ldsm4t(bl, uBase + SO_VL + offBV + kbV);
            mma16(oacc[0], ah,  bh[0], bh[1]);
            mma16(oacc[0], al_, bh[0], bh[1]);
            mma16(oacc[0], ah,  bl[0], bl[1]);
            mma16(oacc[1], ah,  bh[2], bh[3]);
            mma16(oacc[1], al_, bh[2], bh[3]);
            mma16(oacc[1], ah,  bl[2], bl[3]);
        }
    }

    // ---- normalize + write output ----
    __syncthreads();
    float inv0 = 1.0f / l_s[lr0];
    float inv1 = 1.0f / l_s[lr1];
#pragma unroll
    for (int nt = 0; nt < 2; nt++) {
        int col = nq * 16 + nt * 8 + 2 * m;
        size_t o0 = ((size_t)h * SS + r0g) * DDIM + col;
        *(float2*)&out[o0]            = make_float2(oacc[nt][0] * inv0, oacc[nt][1] * inv0);
        *(float2*)&out[o0 + 8 * DDIM] = make_float2(oacc[nt][2] * inv1, oacc[nt][3] * inv1);
    }
}

// ---------------------------------------------------------------------------
extern "C" void kernel_launch(void* const* d_in, const int* in_sizes, int n_in,
                              void* d_out, int out_size)
{
    const float* Q      = (const float*)d_in[0];
    const float* K      = (const float*)d_in[1];
    const float* V      = (const float*)d_in[2];
    const float* dist   = (const float*)d_in[3];
    const float* energy = (const float*)d_in[4];
    const int*   mask   = (const int*)  d_in[5];
    const float* mu_D   = (const float*)d_in[6];
    const float* sg_D   = (const float*)d_in[7];
    const float* b_D    = (const float*)d_in[8];
    const float* mu_E   = (const float*)d_in[9];
    const float* sg_E   = (const float*)d_in[10];
    const float* b_E    = (const float*)d_in[11];
    const float* W1     = (const float*)d_in[12];
    const float* b1     = (const float*)d_in[13];
    const float* W2     = (const float*)d_in[14];
    const float* b2     = (const float*)d_in[15];
    float* out = (float*)d_out;

    build_lut_kernel<<<(2 * NLUT + 255) / 256, 256>>>(
        mu_D, sg_D, b_D, mu_E, sg_E, b_E, W1, b1, W2, b2);

    cudaFuncSetAttribute(attn_kernel,
                         cudaFuncAttributeMaxDynamicSharedMemorySize, SMEM_TOTAL);
    attn_kernel<<<dim3(SS / BM, HH), 256, SMEM_TOTAL>>>(
        Q, K, V, dist, energy, mask, out);
}